// round 4
// baseline (speedup 1.0000x reference)
#include <cuda_runtime.h>

// LSTM_21869973471591 — B=4096, T=200, IN=2, H=64 (gates 4H=256)
//
// R4 = R3 layout + R2 occupancy:
//   - 256-thread CTAs: 4 row-groups (tid>>6) map 1:1 to the 4 gate types for
//     the W transpose; each thread owns hidden unit n for RM=4 batch rows.
//   - NB=16 rows/CTA, grid=256 (4096 exactly), smem 87KB -> 2 CTAs/SM,
//     16 warps/SM (4/SMSP) — fixes R3's occ=12% starvation.
//   - inner loop consumes TWO k's per iter: one LDS.128 of pre-duplicated
//     {h_k,h_k,h_k+1,h_k+1} + two LDS.128 of gate-interleaved W -> mix
//     6 LDS : 16 fma2 (73% fma share).
//   - activation fully in-register (c in regs), h double-buffered in smem,
//     ONE __syncthreads per timestep.

#define B_TOT  4096
#define T_LEN  200
#define H_DIM  64
#define NB     16
#define RM     4            // rows per thread
#define CH     20           // x staging chunk (200 % 20 == 0)
#define NTH    256
#define GRID   (B_TOT / NB) // 256

// dynamic smem layout (bytes)
#define OFF_W   0
#define SZ_W    (64 * 64 * 16)          // Wt4[k][n] = {wi,wf,wg,wo}   65536
#define OFF_HD  (OFF_W + SZ_W)
#define SZ_HD   (2 * NB * 64 * 8)       // hd[2][NB][64] {h,h}         16384
#define OFF_XD  (OFF_HD + SZ_HD)
#define SZ_XD   (NB * CH * 16)          // xd[NB][CH] {x0,x0,x1,x1}     5120
#define SMEM_TOTAL (OFF_XD + SZ_XD)     // 87040 B -> 2 CTAs/SM

typedef unsigned long long u64;

__device__ __forceinline__ u64 pack2(float lo, float hi) {
    u64 r; asm("mov.b64 %0, {%1, %2};" : "=l"(r) : "f"(lo), "f"(hi)); return r;
}
__device__ __forceinline__ void unpack2(u64 v, float& lo, float& hi) {
    asm("mov.b64 {%0, %1}, %2;" : "=f"(lo), "=f"(hi) : "l"(v));
}
__device__ __forceinline__ void fma2(u64& acc, u64 a, u64 b) {
    asm("fma.rn.f32x2 %0, %1, %2, %0;" : "+l"(acc) : "l"(a), "l"(b));
}
__device__ __forceinline__ float fast_rcp(float x) {
    float r; asm("rcp.approx.f32 %0, %1;" : "=f"(r) : "f"(x)); return r;
}
__device__ __forceinline__ float fast_ex2(float x) {
    float r; asm("ex2.approx.f32 %0, %1;" : "=f"(r) : "f"(x)); return r;
}
// accurate sigmoid/tanh via ex2.approx (~2^-22) + rcp.approx; validated
// rel_err ~3e-7 across R1-R3.
__device__ __forceinline__ float sigmoid_f(float x) {
    float e = fast_ex2(-1.4426950408889634f * x);
    return fast_rcp(1.0f + e);
}
__device__ __forceinline__ float tanh_f(float x) {
    float e = fast_ex2(2.8853900817779268f * x);
    return fmaf(-2.0f, fast_rcp(1.0f + e), 1.0f);
}

__global__ __launch_bounds__(NTH, 2)
void lstm_kernel(const float* __restrict__ x,      // [B, T, 2]
                 const float* __restrict__ W_ih,   // [256, 2]
                 const float* __restrict__ W_hh,   // [256, 64]
                 const float* __restrict__ b_ih,   // [256]
                 const float* __restrict__ b_hh,   // [256]
                 const float* __restrict__ W_fc,   // [1, 64]
                 const float* __restrict__ b_fc,   // [1]
                 float* __restrict__ out)          // [B, 1]
{
    extern __shared__ char smem[];
    float*            wt_f = (float*)(smem + OFF_W);
    const ulonglong2* wt2  = (const ulonglong2*)(smem + OFF_W);   // [k*64+n] = {wi,wf},{wg,wo}
    u64*              hd   = (u64*)(smem + OFF_HD);               // [(buf*NB+b)*64+k] = {h,h}
    float4*           xd   = (float4*)(smem + OFF_XD);            // [b*CH+tc] = {x0,x0,x1,x1}

    const int tid  = threadIdx.x;
    const int rg   = tid >> 6;          // row-group (and gate type for init) 0..3
    const int n    = tid & 63;          // hidden unit owned by this thread
    const int row0 = blockIdx.x * NB;

    // per-unit W_ih / bias, packed for fma2
    const u64 wx0_if = pack2(W_ih[(n)*2 + 0],       W_ih[(64 + n)*2 + 0]);
    const u64 wx1_if = pack2(W_ih[(n)*2 + 1],       W_ih[(64 + n)*2 + 1]);
    const u64 wx0_go = pack2(W_ih[(128 + n)*2 + 0], W_ih[(192 + n)*2 + 0]);
    const u64 wx1_go = pack2(W_ih[(128 + n)*2 + 1], W_ih[(192 + n)*2 + 1]);
    const u64 bias_if = pack2(b_ih[n] + b_hh[n],             b_ih[64 + n] + b_hh[64 + n]);
    const u64 bias_go = pack2(b_ih[128 + n] + b_hh[128 + n], b_ih[192 + n] + b_hh[192 + n]);

    // transpose W_hh -> Wt4[k][n] = {Wi,Wf,Wg,Wo}[n][k]; row-group rg loads gate rg
    {
        const float4* wrow = (const float4*)(W_hh + (rg * 64 + n) * 64);
        #pragma unroll
        for (int k4 = 0; k4 < 16; k4++) {
            float4 v = wrow[k4];
            wt_f[((4*k4 + 0) * 64 + n) * 4 + rg] = v.x;
            wt_f[((4*k4 + 1) * 64 + n) * 4 + rg] = v.y;
            wt_f[((4*k4 + 2) * 64 + n) * 4 + rg] = v.z;
            wt_f[((4*k4 + 3) * 64 + n) * 4 + rg] = v.w;
        }
    }
    // h = 0 (both buffers)
    for (int i = tid; i < 2 * NB * 64; i += NTH) hd[i] = 0ull;

    float c[RM];
    #pragma unroll
    for (int b = 0; b < RM; b++) c[b] = 0.0f;

    __syncthreads();

    for (int t = 0; t < T_LEN; t++) {
        const int tc = t % CH;
        if (tc == 0) {
            // stage x[t..t+CH) duplicated: {x0,x0,x1,x1}
            for (int idx = tid; idx < NB * CH; idx += NTH) {
                int b = idx / CH, cc = idx - b * CH;
                float2 xv = *(const float2*)(x + ((row0 + b) * T_LEN + t + cc) * 2);
                xd[b * CH + cc] = make_float4(xv.x, xv.x, xv.y, xv.y);
            }
            __syncthreads();
        }

        const int p = t & 1;
        const u64* hrd = hd + (p * NB + rg * RM) * 64;

        // ---- gate phase: packed accumulators {i,f} and {g,o} for 4 rows ----
        u64 aif[RM], ago[RM];
        #pragma unroll
        for (int b = 0; b < RM; b++) {
            ulonglong2 xq = *(const ulonglong2*)&xd[(rg * RM + b) * CH + tc];
            u64 a0 = bias_if; fma2(a0, wx0_if, xq.x); fma2(a0, wx1_if, xq.y);
            u64 a1 = bias_go; fma2(a1, wx0_go, xq.x); fma2(a1, wx1_go, xq.y);
            aif[b] = a0; ago[b] = a1;
        }
        #pragma unroll 4
        for (int m = 0; m < H_DIM / 2; m++) {        // k = 2m, 2m+1
            ulonglong2 w0 = wt2[(2*m)     * 64 + n]; // {wi,wf},{wg,wo} @ k
            ulonglong2 w1 = wt2[(2*m + 1) * 64 + n]; // {wi,wf},{wg,wo} @ k+1
            #pragma unroll
            for (int b = 0; b < RM; b++) {
                ulonglong2 hq = *(const ulonglong2*)&hrd[b * 64 + 2*m]; // {hk,hk},{hk1,hk1}
                fma2(aif[b], w0.x, hq.x);
                fma2(ago[b], w0.y, hq.x);
                fma2(aif[b], w1.x, hq.y);
                fma2(ago[b], w1.y, hq.y);
            }
        }

        // ---- activation, fully in-register; write h for step t+1 ----
        u64* hwr = hd + ((1 - p) * NB + rg * RM) * 64;
        #pragma unroll
        for (int b = 0; b < RM; b++) {
            float gi, gf, gg, go_;
            unpack2(aif[b], gi, gf);
            unpack2(ago[b], gg, go_);
            float iv = sigmoid_f(gi);
            float fv = sigmoid_f(gf);
            float ov = sigmoid_f(go_);
            float gv = tanh_f(gg);
            float cv = fmaf(fv, c[b], iv * gv);
            c[b] = cv;
            float h = ov * tanh_f(cv);
            hwr[b * 64 + n] = pack2(h, h);
        }
        __syncthreads();
    }

    // final h is in buffer 0 (t=199 writes buf 1-(199&1)=0)
    if (tid < NB) {
        float s = b_fc[0];
        const u64* hrow = hd + tid * 64;
        #pragma unroll
        for (int k = 0; k < H_DIM; k++) {
            float lo, hi; unpack2(hrow[k], lo, hi); (void)hi;
            s = fmaf(lo, W_fc[k], s);
        }
        out[row0 + tid] = s;
    }
}

extern "C" void kernel_launch(void* const* d_in, const int* in_sizes, int n_in,
                              void* d_out, int out_size) {
    const float* x    = (const float*)d_in[0];
    const float* W_ih = (const float*)d_in[1];
    const float* W_hh = (const float*)d_in[2];
    const float* b_ih = (const float*)d_in[3];
    const float* b_hh = (const float*)d_in[4];
    const float* W_fc = (const float*)d_in[5];
    const float* b_fc = (const float*)d_in[6];
    float* out = (float*)d_out;
    (void)in_sizes; (void)n_in; (void)out_size;

    static int attr_set = 0;
    if (!attr_set) {
        cudaFuncSetAttribute(lstm_kernel,
                             cudaFuncAttributeMaxDynamicSharedMemorySize,
                             SMEM_TOTAL);
        attr_set = 1;
    }
    lstm_kernel<<<GRID, NTH, SMEM_TOTAL>>>(x, W_ih, W_hh, b_ih, b_hh,
                                           W_fc, b_fc, out);
}